// round 14
// baseline (speedup 1.0000x reference)
#include <cuda_runtime.h>
#include <cuda.h>
#include <dlfcn.h>
#include <cstdint>

// Problem constants (fixed by the dataset)
#define NN      262144            // nodes per tree (2^18)
#define NT      12                // B*C trees
#define HWPX    1048576           // H*W (2^20)
#define T0      2048              // exactly-solved prefix per tree (2^11)
#define TOTAL   (NT * NN)
#define NPIX    (NT * HWPX)

#define S3_LO   131072
#define S3_TREE ((NN - S3_LO) / 256)        // 512 blocks/tree
#define GB_TREE (HWPX / 4 / 256)            // 1024 gather blocks/tree (fallback)
#define TMA_BLOCKS (NPIX / 4 / 256)         // 12288 blocks, 1024 px/block

// Scratch (allocation-free rule: __device__ globals)
__device__ float4 g_node[TOTAL];   // {c0,c1,c2,parent-as-float-bits}
__device__ float4 g_F[TOTAL];      // final {f0,f1,f2,_}; viewed by TMA as 16B rows

__device__ __forceinline__ float sigmoidf_(float x) {
    return 1.0f / (1.0f + expf(-x));
}

__device__ __forceinline__ uint32_t smem_u32(const void* p) {
    uint32_t a;
    asm("{ .reg .u64 t; cvta.to.shared.u64 t, %1; cvt.u32.u64 %0, t; }"
        : "=r"(a) : "l"(p));
    return a;
}

// ---------------------------------------------------------------------------
// Contrib math for one quad (4 nodes): returns 4 packed node records.
// ---------------------------------------------------------------------------
__device__ __forceinline__ void contrib_quad(
        const float4* __restrict__ attrs4, const float4* __restrict__ residue4,
        const int4* __restrict__ parent4, size_t q,
        float w0, float w10, float w11, float w2,
        float B0, float B1, float B2, float4 rec[4]) {
    float4 A0 = __ldcs(&attrs4[3 * q + 0]);
    float4 A1 = __ldcs(&attrs4[3 * q + 1]);
    float4 A2 = __ldcs(&attrs4[3 * q + 2]);
    float4 R  = __ldcs(&residue4[q]);
    int4   P  = __ldcs(&parent4[q]);

    float a0[4] = {A0.x, A0.w, A1.z, A2.y};
    float a1[4] = {A0.y, A1.x, A1.w, A2.z};
    float a2[4] = {A0.z, A1.y, A2.x, A2.w};
    float r[4]  = {R.x, R.y, R.z, R.w};
    int   p[4]  = {P.x, P.y, P.z, P.w};

#pragma unroll
    for (int k = 0; k < 4; k++) {
        float c0 = sigmoidf_(fmaf(a0[k], w0, B0)) * r[k];
        float c1 = sigmoidf_(fmaf(a2[k], w11, fmaf(a1[k], w10, B1))) * r[k];
        float c2 = sigmoidf_(fmaf(a1[k], w2, B2)) * r[k];
        rec[k] = make_float4(c0, c1, c2, __int_as_float(p[k]));
    }
}

// ---------------------------------------------------------------------------
// K1: contrib (all nodes) + exact prefix solve for [0,T0) (12 special blocks).
// ---------------------------------------------------------------------------
__global__ void k_contrib_prefix(const float4* __restrict__ attrs4,
                                 const float4* __restrict__ residue4,
                                 const int4*  __restrict__ parent4,
                                 const float* __restrict__ W0,
                                 const float* __restrict__ W1,
                                 const float* __restrict__ W2,
                                 const float* __restrict__ b0,
                                 const float* __restrict__ b1,
                                 const float* __restrict__ b2) {
    __shared__ float4 sm[T0];

    const float w0  = __ldg(W0);
    const float w10 = __ldg(&W1[0]);
    const float w11 = __ldg(&W1[1]);
    const float w2  = __ldg(W2);
    const float B0 = __ldg(b0), B1 = __ldg(b1), B2 = __ldg(b2);

    if (blockIdx.x >= NT) {
        size_t q = (size_t)(blockIdx.x - NT) * blockDim.x + threadIdx.x;
        float4 rec[4];
        contrib_quad(attrs4, residue4, parent4, q,
                     w0, w10, w11, w2, B0, B1, B2, rec);
        float4* outp = g_node + 4 * q;
#pragma unroll
        for (int k = 0; k < 4; k++) outp[k] = rec[k];
        return;
    }

    const int tree = blockIdx.x;
    const int tid = threadIdx.x;

#pragma unroll
    for (int c = 0; c < 2; c++) {
        int lq = tid + c * 256;
        size_t q = (size_t)tree * (NN / 4) + lq;
        float4 rec[4];
        contrib_quad(attrs4, residue4, parent4, q,
                     w0, w10, w11, w2, B0, B1, B2, rec);
        float4* outp = g_node + 4 * q;
#pragma unroll
        for (int k = 0; k < 4; k++) {
            outp[k] = rec[k];
            sm[4 * lq + k] = rec[k];
        }
    }
    __syncthreads();

    for (int r = 0; r < 11; r++) {
        float4 tmp[8];
#pragma unroll
        for (int k = 0; k < 8; k++) {
            int e = tid + k * 256;
            float4 v = sm[e];
            int p = __float_as_int(v.w);
            if (p < T0) {
                float4 o = sm[p];
                v.x += o.x; v.y += o.y; v.z += o.z; v.w = o.w;
            }
            tmp[k] = v;
        }
        __syncthreads();
#pragma unroll
        for (int k = 0; k < 8; k++) sm[tid + k * 256] = tmp[k];
        __syncthreads();
    }

    float4* Fb = g_F + (size_t)tree * NN;
#pragma unroll
    for (int k = 0; k < 8; k++) {
        int e = tid + k * 256;
        float4 v = sm[e];
        Fb[e] = make_float4(v.x, v.y, v.z, 0.0f);
    }
}

// ---------------------------------------------------------------------------
// Cascade: finalize F for node n in [start, ...) of every tree (gridDim.y=NT).
// ---------------------------------------------------------------------------
__global__ void k_cascade(int start) {
    const int tree = blockIdx.y;
    const int n = start + blockIdx.x * blockDim.x + threadIdx.x;

    const float4* nb = g_node + (size_t)tree * NN;
    float4*       Fb = g_F    + (size_t)tree * NN;

    float4 v = __ldg(&nb[n]);
    float ax = v.x, ay = v.y, az = v.z;
    int p = __float_as_int(v.w);

    while (p >= start) {
        float4 u = __ldg(&nb[p]);
        ax += u.x; ay += u.y; az += u.z;
        p = __float_as_int(u.w);
    }
    float4 f = __ldg(&Fb[p]);
    Fb[n] = make_float4(ax + f.x, ay + f.y, az + f.z, 0.0f);
}

// ---------------------------------------------------------------------------
// TMA gather kernel: each thread's 4 pixels = one tile::gather4 (4 random
// 16B rows of g_F) into its 128B smem slot; block mbarrier; rotated LDS
// readback; coalesced per-channel float4 stores.
// ---------------------------------------------------------------------------
__global__ void __launch_bounds__(256)
k_gather_tma(const __grid_constant__ CUtensorMap tmap,
             const int4* __restrict__ pix4,
             float* __restrict__ out) {
    __shared__ alignas(128) uint8_t buf[256 * 128];
    __shared__ uint64_t mbar;

    const int tid = threadIdx.x;
    const size_t gq = (size_t)blockIdx.x * 256 + tid;     // quad index, global
    const int tree = (int)(gq >> 18);                     // HWPX/4 = 2^18 quads/tree
    const int lt   = (int)(gq & ((HWPX / 4) - 1));

    int4 nd = __ldcs(&pix4[gq]);

    const uint32_t mb = smem_u32(&mbar);
    if (tid == 0) {
        asm volatile("mbarrier.init.shared.b64 [%0], %1;" :: "r"(mb), "r"(1) : "memory");
        // Make the init visible to the async proxy before any TMA touches it.
        asm volatile("fence.mbarrier_init.release.cluster;" ::: "memory");
        asm volatile("mbarrier.arrive.expect_tx.shared.b64 _, [%0], %1;"
                     :: "r"(mb), "r"(256 * 64) : "memory");
    }
    __syncthreads();   // all gather4 issues happen after init + expect_tx

    const uint32_t slot = smem_u32(buf) + tid * 128;
    const int row0 = tree * NN;
    asm volatile(
        "cp.async.bulk.tensor.2d.tile::gather4.shared::cta.global.mbarrier::complete_tx::bytes "
        "[%0], [%1, {%2, %3, %4, %5, %6}], [%7];"
        :: "r"(slot), "l"((const void*)&tmap), "r"(0),
           "r"(row0 + nd.x), "r"(row0 + nd.y), "r"(row0 + nd.z), "r"(row0 + nd.w),
           "r"(mb)
        : "memory");

    // wait parity 0
    {
        uint32_t done;
        asm volatile(
            "{\n\t.reg .pred p;\n\t"
            "mbarrier.try_wait.parity.acquire.cta.shared::cta.b64 p, [%1], %2;\n\t"
            "selp.b32 %0, 1, 0, p;\n\t}"
            : "=r"(done) : "r"(mb), "r"(0) : "memory");
        if (!done) {
            asm volatile(
                "{\n\t.reg .pred P1;\n\t"
                "W_%=:\n\t"
                "mbarrier.try_wait.parity.acquire.cta.shared::cta.b64 P1, [%0], %1, 0x989680;\n\t"
                "@P1 bra.uni D_%=;\n\t"
                "bra.uni W_%=;\n\t"
                "D_%=:\n\t}"
                :: "r"(mb), "r"(0) : "memory");
        }
    }

    // Rotated readback: lane groups read different 16B sub-slots per step.
    float4 F[4];
    const float4* s4 = (const float4*)(buf + tid * 128);
#pragma unroll
    for (int j = 0; j < 4; j++) {
        int k = ((tid & 3) + j) & 3;
        F[k] = s4[k];
    }

    float* o = out + (size_t)tree * 3 * HWPX + 4 * (size_t)lt;
    __stcs((float4*)(o),            make_float4(F[0].x, F[1].x, F[2].x, F[3].x));
    __stcs((float4*)(o + HWPX),     make_float4(F[0].y, F[1].y, F[2].y, F[3].y));
    __stcs((float4*)(o + 2 * HWPX), make_float4(F[0].z, F[1].z, F[2].z, F[3].z));
}

// ---------------------------------------------------------------------------
// Fallback LDG gather (proven path) — used if tensormap encode fails.
// ---------------------------------------------------------------------------
__global__ void k_gather_ldg(const int4* __restrict__ pix4,
                             float* __restrict__ out) {
    const int bid = blockIdx.x;
    const int tree = bid / GB_TREE;
    const int lt = (bid % GB_TREE) * 256 + threadIdx.x;

    int4 nd = __ldcs(&pix4[(size_t)tree * (HWPX / 4) + lt]);

    const float4* Fb = g_F + (size_t)tree * NN;
    float4 F0 = __ldg(&Fb[nd.x]);
    float4 F1 = __ldg(&Fb[nd.y]);
    float4 F2 = __ldg(&Fb[nd.z]);
    float4 F3 = __ldg(&Fb[nd.w]);

    float* o = out + (size_t)tree * 3 * HWPX + 4 * (size_t)lt;
    __stcs((float4*)(o),            make_float4(F0.x, F1.x, F2.x, F3.x));
    __stcs((float4*)(o + HWPX),     make_float4(F0.y, F1.y, F2.y, F3.y));
    __stcs((float4*)(o + 2 * HWPX), make_float4(F0.z, F1.z, F2.z, F3.z));
}

// ---------------------------------------------------------------------------
// Host-side tensormap encode via dlopen (no -lcuda link dependency).
// gather4-canonical config: rank 2, boxDim {4,1}, SWIZZLE_NONE,
// L2_PROMOTION_NONE (promotion would 8x the random 16B-row traffic).
// ---------------------------------------------------------------------------
typedef CUresult (*PFN_tmEncode)(
    CUtensorMap*, CUtensorMapDataType, cuuint32_t, void*,
    const cuuint64_t*, const cuuint64_t*, const cuuint32_t*, const cuuint32_t*,
    CUtensorMapInterleave, CUtensorMapSwizzle, CUtensorMapL2promotion,
    CUtensorMapFloatOOBfill);

static bool encode_tmap(CUtensorMap* tm) {
    void* gF = nullptr;
    if (cudaGetSymbolAddress(&gF, g_F) != cudaSuccess || !gF) return false;

    void* h = dlopen("libcuda.so.1", RTLD_NOW | RTLD_GLOBAL);
    if (!h) h = dlopen("libcuda.so", RTLD_NOW | RTLD_GLOBAL);
    if (!h) return false;
    PFN_tmEncode fn = (PFN_tmEncode)dlsym(h, "cuTensorMapEncodeTiled");
    if (!fn) return false;

    cuuint64_t dims[2]    = {4ULL, (cuuint64_t)TOTAL};   // 4 floats x 3.1M rows
    cuuint64_t strides[1] = {16ULL};                     // 16B row stride
    cuuint32_t es[2]      = {1, 1};
    cuuint32_t box41[2]   = {4, 1};                      // gather4: box height 1

    return fn(tm, CU_TENSOR_MAP_DATA_TYPE_FLOAT32, 2, gF, dims, strides, box41, es,
              CU_TENSOR_MAP_INTERLEAVE_NONE, CU_TENSOR_MAP_SWIZZLE_NONE,
              CU_TENSOR_MAP_L2_PROMOTION_NONE,
              CU_TENSOR_MAP_FLOAT_OOB_FILL_NONE) == CUDA_SUCCESS;
}

// ---------------------------------------------------------------------------
// Entry point — 5 serial launches:
//   K1 contrib+prefix; K2 s01 [2048,32K); K3 s2 [32K,131K); K4 s3 [131K,256K);
//   K5 gather (TMA gather4, LDG fallback if encode failed).
// Inputs: attrs, residue, W0, W1, W2, b0, b1, b2, parent, pixel_node
// ---------------------------------------------------------------------------
extern "C" void kernel_launch(void* const* d_in, const int* in_sizes, int n_in,
                              void* d_out, int out_size) {
    const float4* attrs4   = (const float4*)d_in[0];
    const float4* residue4 = (const float4*)d_in[1];
    const float* W0        = (const float*)d_in[2];
    const float* W1        = (const float*)d_in[3];
    const float* W2        = (const float*)d_in[4];
    const float* b0        = (const float*)d_in[5];
    const float* b1        = (const float*)d_in[6];
    const float* b2        = (const float*)d_in[7];
    const int4*  parent4   = (const int4*)d_in[8];
    const int4*  pix4      = (const int4*)d_in[9];
    float*       out       = (float*)d_out;

    CUtensorMap tmap;
    const bool tma_ok = encode_tmap(&tmap);   // host-only, deterministic, capture-safe

    // K1
    k_contrib_prefix<<<NT + TOTAL / 4 / 256, 256>>>(attrs4, residue4, parent4,
                                                    W0, W1, W2, b0, b1, b2);
    // K2: s01 [2048, 32768)
    {
        dim3 grid((32768 - 2048) / 256, NT);
        k_cascade<<<grid, 256>>>(2048);
    }
    // K3: s2 [32768, 131072)
    {
        dim3 grid((131072 - 32768) / 256, NT);
        k_cascade<<<grid, 256>>>(32768);
    }
    // K4: s3 [131072, 262144), full width
    {
        dim3 grid(S3_TREE, NT);
        k_cascade<<<grid, 256>>>(S3_LO);
    }
    // K5: gather
    if (tma_ok) {
        k_gather_tma<<<TMA_BLOCKS, 256>>>(tmap, pix4, out);
    } else {
        k_gather_ldg<<<NT * GB_TREE, 256>>>(pix4, out);
    }
}

// round 15
// speedup vs baseline: 1.4113x; 1.4113x over previous
#include <cuda_runtime.h>

// Problem constants (fixed by the dataset)
#define NN      262144            // nodes per tree (2^18)
#define NT      12                // B*C trees
#define HWPX    1048576           // H*W (2^20)
#define T0      2048              // exactly-solved prefix per tree (2^11)
#define TOTAL   (NT * NN)

#define S3_LO   131072
#define S3_TREE ((NN - S3_LO) / 256)        // 512 s3 blocks/tree
#define GB_TREE (HWPX / 4 / 256)            // 1024 gather blocks/tree

// Scratch (allocation-free rule: __device__ globals)
__device__ float4 g_node[TOTAL];   // {c0,c1,c2,parent-as-float-bits}
__device__ float4 g_F[TOTAL];      // final {f0,f1,f2,_}

__device__ __forceinline__ float sigmoidf_(float x) {
    return 1.0f / (1.0f + expf(-x));
}

// ---------------------------------------------------------------------------
// Contrib math for one quad (4 nodes): returns 4 packed node records.
// ---------------------------------------------------------------------------
__device__ __forceinline__ void contrib_quad(
        const float4* __restrict__ attrs4, const float4* __restrict__ residue4,
        const int4* __restrict__ parent4, size_t q,
        float w0, float w10, float w11, float w2,
        float B0, float B1, float B2, float4 rec[4]) {
    float4 A0 = __ldcs(&attrs4[3 * q + 0]);   // a0[0] a1[0] a2[0] a0[1]
    float4 A1 = __ldcs(&attrs4[3 * q + 1]);   // a1[1] a2[1] a0[2] a1[2]
    float4 A2 = __ldcs(&attrs4[3 * q + 2]);   // a2[2] a0[3] a1[3] a2[3]
    float4 R  = __ldcs(&residue4[q]);
    int4   P  = __ldcs(&parent4[q]);

    float a0[4] = {A0.x, A0.w, A1.z, A2.y};
    float a1[4] = {A0.y, A1.x, A1.w, A2.z};
    float a2[4] = {A0.z, A1.y, A2.x, A2.w};
    float r[4]  = {R.x, R.y, R.z, R.w};
    int   p[4]  = {P.x, P.y, P.z, P.w};

#pragma unroll
    for (int k = 0; k < 4; k++) {
        float c0 = sigmoidf_(fmaf(a0[k], w0, B0)) * r[k];
        float c1 = sigmoidf_(fmaf(a2[k], w11, fmaf(a1[k], w10, B1))) * r[k];
        float c2 = sigmoidf_(fmaf(a1[k], w2, B2)) * r[k];
        rec[k] = make_float4(c0, c1, c2, __int_as_float(p[k]));
    }
}

// ---------------------------------------------------------------------------
// K1: contrib (all nodes) + exact prefix solve for [0,T0) (12 special blocks).
// ---------------------------------------------------------------------------
__global__ void k_contrib_prefix(const float4* __restrict__ attrs4,
                                 const float4* __restrict__ residue4,
                                 const int4*  __restrict__ parent4,
                                 const float* __restrict__ W0,
                                 const float* __restrict__ W1,
                                 const float* __restrict__ W2,
                                 const float* __restrict__ b0,
                                 const float* __restrict__ b1,
                                 const float* __restrict__ b2) {
    __shared__ float4 sm[T0];

    const float w0  = __ldg(W0);
    const float w10 = __ldg(&W1[0]);
    const float w11 = __ldg(&W1[1]);
    const float w2  = __ldg(W2);
    const float B0 = __ldg(b0), B1 = __ldg(b1), B2 = __ldg(b2);

    if (blockIdx.x >= NT) {
        // ---- normal contrib block ----
        size_t q = (size_t)(blockIdx.x - NT) * blockDim.x + threadIdx.x;
        float4 rec[4];
        contrib_quad(attrs4, residue4, parent4, q,
                     w0, w10, w11, w2, B0, B1, B2, rec);
        float4* outp = g_node + 4 * q;
#pragma unroll
        for (int k = 0; k < 4; k++) outp[k] = rec[k];
        return;
    }

    // ---- special block: contrib for [0,T0) + Wyllie prefix ----
    const int tree = blockIdx.x;
    const int tid = threadIdx.x;

#pragma unroll
    for (int c = 0; c < 2; c++) {
        int lq = tid + c * 256;                       // local quad 0..511
        size_t q = (size_t)tree * (NN / 4) + lq;
        float4 rec[4];
        contrib_quad(attrs4, residue4, parent4, q,
                     w0, w10, w11, w2, B0, B1, B2, rec);
        float4* outp = g_node + 4 * q;
#pragma unroll
        for (int k = 0; k < 4; k++) {
            outp[k] = rec[k];
            sm[4 * lq + k] = rec[k];
        }
    }
    __syncthreads();

    for (int r = 0; r < 11; r++) {
        float4 tmp[8];
#pragma unroll
        for (int k = 0; k < 8; k++) {
            int e = tid + k * 256;
            float4 v = sm[e];
            int p = __float_as_int(v.w);
            if (p < T0) {
                float4 o = sm[p];
                v.x += o.x; v.y += o.y; v.z += o.z; v.w = o.w;
            }
            tmp[k] = v;
        }
        __syncthreads();
#pragma unroll
        for (int k = 0; k < 8; k++) sm[tid + k * 256] = tmp[k];
        __syncthreads();
    }

    float4* Fb = g_F + (size_t)tree * NN;
#pragma unroll
    for (int k = 0; k < 8; k++) {
        int e = tid + k * 256;
        float4 v = sm[e];
        Fb[e] = make_float4(v.x, v.y, v.z, 0.0f);
    }
}

// ---------------------------------------------------------------------------
// Cascade body: finalize F for node n of `tree`; everything below `start`
// is already final in g_F.
// ---------------------------------------------------------------------------
__device__ __forceinline__ void cascade_body(int tree, int start, int n) {
    const float4* nb = g_node + (size_t)tree * NN;
    float4*       Fb = g_F    + (size_t)tree * NN;

    float4 v = __ldg(&nb[n]);
    float ax = v.x, ay = v.y, az = v.z;
    int p = __float_as_int(v.w);

    while (p >= start) {
        float4 u = __ldg(&nb[p]);
        ax += u.x; ay += u.y; az += u.z;
        p = __float_as_int(u.w);
    }
    float4 f = __ldg(&Fb[p]);
    Fb[n] = make_float4(ax + f.x, ay + f.y, az + f.z, 0.0f);
}

// Full-width cascade kernel: all trees (gridDim.y = NT)
__global__ void k_cascade(int start) {
    const int tree = blockIdx.y;
    const int n = start + blockIdx.x * blockDim.x + threadIdx.x;
    cascade_body(tree, start, n);
}

// Group s3 kernel: trees [base, base+gridDim.y)
__global__ void k_s3_grp(int base) {
    const int tree = base + blockIdx.y;
    const int n = S3_LO + blockIdx.x * blockDim.x + threadIdx.x;
    cascade_body(tree, S3_LO, n);
}

// ---------------------------------------------------------------------------
// Gather body: 4 pixels/thread for `tree`; one 16B gather serves all 3
// output channels; coalesced float4 stores per channel plane.
// ---------------------------------------------------------------------------
__device__ __forceinline__ void gather_body(int tree, int lt,
                                            const int4* __restrict__ pix4,
                                            float* __restrict__ out) {
    int4 nd = __ldcs(&pix4[(size_t)tree * (HWPX / 4) + lt]);

    const float4* Fb = g_F + (size_t)tree * NN;
    float4 F0 = __ldg(&Fb[nd.x]);
    float4 F1 = __ldg(&Fb[nd.y]);
    float4 F2 = __ldg(&Fb[nd.z]);
    float4 F3 = __ldg(&Fb[nd.w]);

    float* o = out + (size_t)tree * 3 * HWPX + 4 * (size_t)lt;
    __stcs((float4*)(o),            make_float4(F0.x, F1.x, F2.x, F3.x));
    __stcs((float4*)(o + HWPX),     make_float4(F0.y, F1.y, F2.y, F3.y));
    __stcs((float4*)(o + 2 * HWPX), make_float4(F0.z, F1.z, F2.z, F3.z));
}

// ---------------------------------------------------------------------------
// Mixed-role kernel: first `gblocks` blocks gather trees [gbase..), remaining
// blocks run the s3 stage of trees [s3base..). All blocks runnable at launch
// (deps completed in prior kernels). Gather blocks take the low bids so the
// long-pole work launches first.
// ---------------------------------------------------------------------------
__global__ void k_mix(int gbase, int gblocks, int s3base,
                      const int4* __restrict__ pix4,
                      float* __restrict__ out) {
    int bid = blockIdx.x;

    if (bid < gblocks) {
        const int tree = gbase + bid / GB_TREE;
        const int lt = (bid % GB_TREE) * 256 + threadIdx.x;
        gather_body(tree, lt, pix4, out);
        return;
    }
    bid -= gblocks;
    {
        const int tree = s3base + bid / S3_TREE;
        const int n = S3_LO + (bid % S3_TREE) * 256 + threadIdx.x;
        cascade_body(tree, S3_LO, n);
    }
}

// ---------------------------------------------------------------------------
// Entry point — 8 serial launches. R12 structure with a smaller exposed s3
// head (2 trees) and group pipeline (2,4,4,2):
//   K1 contrib+prefix; K2 s01 [2048,32K) all; K3 s2 [32K,131K) all;
//   K4 s3 trees{0,1};
//   K5 gather(0,1)||s3(2..5); K6 gather(2..5)||s3(6..9);
//   K7 gather(6..9)||s3(10,11); K8 gather(10,11)
// Inputs: attrs, residue, W0, W1, W2, b0, b1, b2, parent, pixel_node
// ---------------------------------------------------------------------------
extern "C" void kernel_launch(void* const* d_in, const int* in_sizes, int n_in,
                              void* d_out, int out_size) {
    const float4* attrs4   = (const float4*)d_in[0];
    const float4* residue4 = (const float4*)d_in[1];
    const float* W0        = (const float*)d_in[2];
    const float* W1        = (const float*)d_in[3];
    const float* W2        = (const float*)d_in[4];
    const float* b0        = (const float*)d_in[5];
    const float* b1        = (const float*)d_in[6];
    const float* b2        = (const float*)d_in[7];
    const int4*  parent4   = (const int4*)d_in[8];
    const int4*  pix4      = (const int4*)d_in[9];
    float*       out       = (float*)d_out;

    // K1: contrib (all trees) + prefix solve (12 special blocks, bids 0..11)
    k_contrib_prefix<<<NT + TOTAL / 4 / 256, 256>>>(attrs4, residue4, parent4,
                                                    W0, W1, W2, b0, b1, b2);
    // K2: s01 [2048, 32768), all trees
    {
        dim3 grid((32768 - 2048) / 256, NT);
        k_cascade<<<grid, 256>>>(2048);
    }
    // K3: s2 [32768, 131072), all trees
    {
        dim3 grid((131072 - 32768) / 256, NT);
        k_cascade<<<grid, 256>>>(32768);
    }
    // K4: s3 trees {0,1} — minimized exposed pipeline head
    {
        dim3 grid(S3_TREE, 2);
        k_s3_grp<<<grid, 256>>>(0);
    }
    // K5: gather(0,1) || s3(2..5)
    k_mix<<<2 * GB_TREE + 4 * S3_TREE, 256>>>(0, 2 * GB_TREE, 2, pix4, out);
    // K6: gather(2..5) || s3(6..9)
    k_mix<<<4 * GB_TREE + 4 * S3_TREE, 256>>>(2, 4 * GB_TREE, 6, pix4, out);
    // K7: gather(6..9) || s3(10,11)
    k_mix<<<4 * GB_TREE + 2 * S3_TREE, 256>>>(6, 4 * GB_TREE, 10, pix4, out);
    // K8: gather(10,11), pure
    k_mix<<<2 * GB_TREE, 256>>>(10, 2 * GB_TREE, 0 /*unused*/, pix4, out);
}